// round 10
// baseline (speedup 1.0000x reference)
#include <cuda_runtime.h>
#include <stdint.h>

#define BN      16384
#define IN_DIM  256
#define HID     128
#define NCLS    8
#define T_STEPS 64
#define BETA    0.9f
#define NSM     148

// Scratch (no cudaMalloc allowed)
__device__ uint4 g_masks[T_STEPS * BN];     // 16 MB  [t][s] spike masks
__device__ float g_W1T[IN_DIM * HID];       // 128 KB W1 transposed: [k][h]

// ---------------------------------------------------------------------------
// K0: W1T[k][h] = W1[h][k]
// ---------------------------------------------------------------------------
__global__ __launch_bounds__(256) void k0_w1t(const float* __restrict__ W1)
{
    int idx = blockIdx.x * 256 + threadIdx.x;
    int h = idx & (HID - 1);
    int k = idx >> 7;
    g_W1T[k * HID + h] = W1[h * IN_DIM + k];
}

// ---------------------------------------------------------------------------
// K12: fused fc1 GEMM (phase A, bitwise == R9 k1) + layer-1 LIF/ballot
// (phase B, bitwise == R9 k2, cur1 sourced from smem instead of global).
// CTA: 64 samples x 128 hid, 256 threads.
// Dynamic smem layout (59392 B):
//   [0      : 16384) ws   32x128 f32      (phase A)
//   [16384  : 50176) cs   64x132 f32 cur1 (phase A write -> phase B read)
//   [50176  : 59392) xs   64x36 f32       (phase A)   |  overlapped:
//   [50176  : 58368) sm   [64][8][4] u32 mask staging (phase B)
// ---------------------------------------------------------------------------
#define XS_STRIDE 36
#define CS_STRIDE 132

__global__ __launch_bounds__(256) void k12_fc1_lif1(const float* __restrict__ x,
                                                    const float* __restrict__ b1)
{
    extern __shared__ char dsm[];
    float* ws = (float*)dsm;                    // [32][128]
    float* cs = (float*)(dsm + 16384);          // [64][CS_STRIDE]
    float* xs = (float*)(dsm + 50176);          // [64][XS_STRIDE]

    const int tid = threadIdx.x;
    const int bs  = blockIdx.x * 64;
    const int c   = tid & 7;
    const int r   = tid >> 3;

    const int xf0_s = tid >> 3,         xf0_k = (tid & 7) * 4;
    const int xf1_s = (256 + tid) >> 3, xf1_k = ((256 + tid) & 7) * 4;

    float4 px0, px1, pw[4];

    px0 = *(const float4*)&x[(bs + xf0_s) * IN_DIM + xf0_k];
    px1 = *(const float4*)&x[(bs + xf1_s) * IN_DIM + xf1_k];
#pragma unroll
    for (int i = 0; i < 4; i++) {
        int f  = i * 256 + tid;
        int kk = f >> 5;
        int h4 = (f & 31) * 4;
        pw[i] = *(const float4*)&g_W1T[kk * HID + h4];
    }

    float acc[4][8];
#pragma unroll
    for (int i = 0; i < 4; i++)
#pragma unroll
        for (int j = 0; j < 8; j++) acc[i][j] = 0.0f;

    for (int ch = 0; ch < IN_DIM / 32; ch++) {
        *(float4*)&xs[xf0_s * XS_STRIDE + xf0_k] = px0;
        *(float4*)&xs[xf1_s * XS_STRIDE + xf1_k] = px1;
#pragma unroll
        for (int i = 0; i < 4; i++) {
            int f  = i * 256 + tid;
            int kk = f >> 5;
            int h4 = (f & 31) * 4;
            *(float4*)&ws[kk * HID + h4] = pw[i];
        }
        __syncthreads();

        if (ch + 1 < IN_DIM / 32) {
            int kc = (ch + 1) * 32;
            px0 = *(const float4*)&x[(bs + xf0_s) * IN_DIM + kc + xf0_k];
            px1 = *(const float4*)&x[(bs + xf1_s) * IN_DIM + kc + xf1_k];
#pragma unroll
            for (int i = 0; i < 4; i++) {
                int f  = i * 256 + tid;
                int kk = f >> 5;
                int h4 = (f & 31) * 4;
                pw[i] = *(const float4*)&g_W1T[(kc + kk) * HID + h4];
            }
        }

#pragma unroll
        for (int k = 0; k < 32; k += 4) {
            float4 xv[8];
#pragma unroll
            for (int j = 0; j < 8; j++)
                xv[j] = *(const float4*)&xs[(c + 8 * j) * XS_STRIDE + k];
            float4 wv[4];
#pragma unroll
            for (int kk = 0; kk < 4; kk++)
                wv[kk] = *(const float4*)&ws[(k + kk) * HID + r * 4];
#pragma unroll
            for (int kk = 0; kk < 4; kk++) {
                float w0 = wv[kk].x, w1 = wv[kk].y, w2 = wv[kk].z, w3 = wv[kk].w;
#pragma unroll
                for (int j = 0; j < 8; j++) {
                    float xvk = (kk == 0) ? xv[j].x : (kk == 1) ? xv[j].y
                              : (kk == 2) ? xv[j].z : xv[j].w;
                    acc[0][j] = fmaf(w0, xvk, acc[0][j]);
                    acc[1][j] = fmaf(w1, xvk, acc[1][j]);
                    acc[2][j] = fmaf(w2, xvk, acc[2][j]);
                    acc[3][j] = fmaf(w3, xvk, acc[3][j]);
                }
            }
        }
        __syncthreads();
    }

    // epilogue: += b1, store cur1 to smem cs
    {
        float4 b1v = *(const float4*)&b1[r * 4];
#pragma unroll
        for (int j = 0; j < 8; j++) {
            float4 o;
            o.x = acc[0][j] + b1v.x;
            o.y = acc[1][j] + b1v.y;
            o.z = acc[2][j] + b1v.z;
            o.w = acc[3][j] + b1v.w;
            *(float4*)&cs[(c + 8 * j) * CS_STRIDE + r * 4] = o;
        }
    }
    __syncthreads();

    // ---- Phase B: layer-1 LIF + ballots (bitwise == k2), 8 sample octets ----
    uint32_t (*sm)[8][4] = (uint32_t (*)[8][4])(dsm + 50176);

    const int w    = tid >> 5;
    const int lane = tid & 31;
    const int g    = w & 3;
    const int q    = w >> 2;
    const int h    = g * 32 + lane;

    for (int it = 0; it < 8; it++) {
        float cur[4], mem[4];
#pragma unroll
        for (int j = 0; j < 4; j++) {
            cur[j] = cs[(it * 8 + q * 4 + j) * CS_STRIDE + h];
            mem[j] = 0.0f;
        }

        for (int t = 0; t < T_STEPS; t++) {
#pragma unroll
            for (int j = 0; j < 4; j++) {
                float m  = mem[j];
                float rf = (m > 1.0f) ? 1.0f : 0.0f;
                m = fmaf(BETA, m, cur[j]) - rf;
                mem[j] = m;
                unsigned bal = __ballot_sync(0xffffffffu, m > 1.0f);
                if (lane == 0) sm[t][q * 4 + j][g] = bal;
            }
        }
        __syncthreads();

        for (int idx = tid; idx < T_STEPS * 8; idx += 256) {
            int t  = idx >> 3;
            int sl = idx & 7;
            g_masks[t * BN + bs + it * 8 + sl] = *(const uint4*)&sm[t][sl][0];
        }
        __syncthreads();
    }
}

// ---------------------------------------------------------------------------
// K3: fused layer-2 LUT + LIF — UNCHANGED from R9 (61 us, rel_err 0.0).
// ---------------------------------------------------------------------------
static __device__ __forceinline__ float4 f4add(float4 a, float4 b)
{
    return make_float4(a.x + b.x, a.y + b.y, a.z + b.z, a.w + b.w);
}

static __device__ __forceinline__ float4 lut_tree(const float* __restrict__ lut,
                                                  uint4 m, float4 b2v)
{
    uint32_t w[4] = {m.x, m.y, m.z, m.w};
    float4 sg[4];
#pragma unroll
    for (int g = 0; g < 4; g++) {
        const float* lg = &lut[g * 4096];
        uint32_t wg = w[g];
        float4 q0 = *(const float4*)&lg[            ((wg        & 255u) << 2)];
        float4 q1 = *(const float4*)&lg[1 * 1024 + (((wg >> 8)  & 255u) << 2)];
        float4 q2 = *(const float4*)&lg[2 * 1024 + (((wg >> 16) & 255u) << 2)];
        float4 q3 = *(const float4*)&lg[3 * 1024 + ((wg >> 24)          << 2)];
        sg[g] = f4add(f4add(q0, q1), f4add(q2, q3));
    }
    return f4add(f4add(f4add(sg[0], sg[1]), f4add(sg[2], sg[3])), b2v);
}

__global__ __launch_bounds__(128) void k3_lif2(const float* __restrict__ W2,
                                               const float* __restrict__ b2,
                                               float* __restrict__ out)
{
    extern __shared__ float lut[];   // [16][256] float4
    const int tid  = threadIdx.x;
    const int half = blockIdx.x & 1;
    const int bi   = blockIdx.x >> 1;          // 0..147

    {
        const int chunk = tid >> 3;            // 0..15
        const int bbase = (tid & 7) * 32;
        float w[4][8];
#pragma unroll
        for (int cc = 0; cc < 4; cc++)
#pragma unroll
            for (int j = 0; j < 8; j++)
                w[cc][j] = W2[(half * 4 + cc) * HID + chunk * 8 + j];

        for (int i = 0; i < 32; i++) {
            int byt = bbase + i;
            float4 v = make_float4(0.f, 0.f, 0.f, 0.f);
#pragma unroll
            for (int j = 0; j < 8; j++) {
                if ((byt >> j) & 1) {
                    v.x += w[0][j]; v.y += w[1][j];
                    v.z += w[2][j]; v.w += w[3][j];
                }
            }
            *(float4*)&lut[(chunk * 256 + byt) * 4] = v;
        }
    }
    __syncthreads();

    const int s_begin = (bi * BN) / NSM;
    const int s_end   = ((bi + 1) * BN) / NSM;
    const int s       = s_begin + tid;
    if (s >= s_end) return;

    float4 b2v = make_float4(b2[half * 4 + 0], b2[half * 4 + 1],
                             b2[half * 4 + 2], b2[half * 4 + 3]);

    const uint4* mp = &g_masks[s];

    uint4 mb = mp[BN];
    float4 cur = lut_tree(lut, mp[0], b2v);

    float4 mem = make_float4(0.f, 0.f, 0.f, 0.f);
    float4 acc = mem, rst = mem;

#pragma unroll 2
    for (int t = 0; t < T_STEPS - 1; t++) {
        int tp = (t + 2 < T_STEPS) ? (t + 2) : (T_STEPS - 1);
        uint4 mnew = mp[(size_t)tp * BN];

        float4 nxt = lut_tree(lut, mb, b2v);
        mb = mnew;

        mem.x = fmaf(BETA, mem.x, cur.x) - rst.x;
        mem.y = fmaf(BETA, mem.y, cur.y) - rst.y;
        mem.z = fmaf(BETA, mem.z, cur.z) - rst.z;
        mem.w = fmaf(BETA, mem.w, cur.w) - rst.w;
        rst.x = (mem.x > 1.0f) ? 1.0f : 0.0f;
        rst.y = (mem.y > 1.0f) ? 1.0f : 0.0f;
        rst.z = (mem.z > 1.0f) ? 1.0f : 0.0f;
        rst.w = (mem.w > 1.0f) ? 1.0f : 0.0f;
        acc.x += rst.x; acc.y += rst.y; acc.z += rst.z; acc.w += rst.w;

        cur = nxt;
    }

    mem.x = fmaf(BETA, mem.x, cur.x) - rst.x;
    mem.y = fmaf(BETA, mem.y, cur.y) - rst.y;
    mem.z = fmaf(BETA, mem.z, cur.z) - rst.z;
    mem.w = fmaf(BETA, mem.w, cur.w) - rst.w;
    acc.x += (mem.x > 1.0f) ? 1.0f : 0.0f;
    acc.y += (mem.y > 1.0f) ? 1.0f : 0.0f;
    acc.z += (mem.z > 1.0f) ? 1.0f : 0.0f;
    acc.w += (mem.w > 1.0f) ? 1.0f : 0.0f;

    *(float4*)&out[s * 8 + half * 4] = acc;
}

// ---------------------------------------------------------------------------
extern "C" void kernel_launch(void* const* d_in, const int* in_sizes, int n_in,
                              void* d_out, int out_size)
{
    const float* x  = (const float*)d_in[0];
    const float* W1 = (const float*)d_in[1];
    const float* b1 = (const float*)d_in[2];
    const float* W2 = (const float*)d_in[3];
    const float* b2 = (const float*)d_in[4];
    float* out = (float*)d_out;

    k0_w1t<<<(IN_DIM * HID) / 256, 256>>>(W1);

    cudaFuncSetAttribute(k12_fc1_lif1, cudaFuncAttributeMaxDynamicSharedMemorySize, 59392);
    k12_fc1_lif1<<<BN / 64, 256, 59392>>>(x, b1);

    cudaFuncSetAttribute(k3_lif2, cudaFuncAttributeMaxDynamicSharedMemorySize, 65536);
    k3_lif2<<<NSM * 2, 128, 65536>>>(W2, b2, out);
}